// round 16
// baseline (speedup 1.0000x reference)
#include <cuda_runtime.h>
#include <cstdint>

#define H 320
#define W 960
#define HW (H * W)
#define PAD 128   // slack so left-window vector loads can't run past the array

// Fused prep tile config
#define TX 64
#define TY 8
#define SX (TX + 4)
#define SY (TY + 4)

// Disparities per volume block (multiple of 4 for aligned left loads)
#define DPB 16

// Scratch (allocation-free: __device__ globals). Y plane never hits global.
__device__ float g_cbL[HW + PAD], g_cbR[HW + PAD];
__device__ float g_crL[HW + PAD], g_crR[HW + PAD];
__device__ unsigned g_cL[HW + PAD], g_cR[HW + PAD];

// Fused YCbCr + census. One block per 64x8 tile per image (blockIdx.z).
__global__ __launch_bounds__(256) void prep_kernel(const float* __restrict__ left,
                                                   const float* __restrict__ right) {
    int img = blockIdx.z;
    const float* src = img ? right : left;
    float* cb    = img ? g_cbR : g_cbL;
    float* cr    = img ? g_crR : g_crL;
    unsigned* C  = img ? g_cR  : g_cL;

    __shared__ float sY[SY][SX];
    int tx0 = blockIdx.x * TX, ty0 = blockIdx.y * TY;

    // Phase 1: compute Y for tile+halo into smem; write cb/cr for interior.
    for (int idx = threadIdx.x; idx < SX * SY; idx += 256) {
        int sy = idx / SX, sx = idx - sy * SX;
        int gx = tx0 + sx - 2, gy = ty0 + sy - 2;
        float yv = 0.0f;
        if (gx >= 0 && gx < W && gy >= 0 && gy < H) {
            int p = gy * W + gx;
            float r = src[p], g = src[HW + p], b = src[2 * HW + p];
            yv = 0.299f * r + 0.587f * g + 0.114f * b;
            if (sx >= 2 && sx < SX - 2 && sy >= 2 && sy < SY - 2) {
                cb[p] = (b - yv) * 0.564f + 0.5f;
                cr[p] = (r - yv) * 0.713f + 0.5f;
            }
        }
        sY[sy][sx] = yv;
    }
    __syncthreads();

    // Phase 2: census from smem.
    int px = threadIdx.x % TX;
    for (int py = threadIdx.x / TX; py < TY; py += 256 / TX) {
        int gx = tx0 + px, gy = ty0 + py;
        unsigned cen = 0u;
        if (gx >= 2 && gx < W - 2 && gy >= 2 && gy < H - 2) {
            float c = sY[py + 2][px + 2];
            #pragma unroll
            for (int v = 0; v < 5; v++) {
                #pragma unroll
                for (int u = 0; u < 5; u++) {
                    if (v == 1 && u == 1) continue;  // reference skips (1,1), NOT the center
                    cen = (cen << 1) | (sY[py + v][px + u] >= c ? 1u : 0u);
                }
            }
        }
        C[gy * W + gx] = cen;
    }

    // PDL: allow the dependent volume kernel to begin launching.
    asm volatile("griddepcontrol.launch_dependents;");
}

// Grid: (y=H fastest, d-group, channel). Per block: lanes 0..239 produce 4
// consecutive x for ONE channel across DPB=16 disparities. Left window =
// 5 aligned vector loads + 1 right load = 6 loads per 16 vector stores
// (0.375 load/store ratio vs 0.5 at DPB=8) -> cuts L1 byte traffic, which
// is the highest-utilization pipe (77.1%). Stores use .cs streaming.
// Out-of-range lanes read neighbor-row garbage (masked on output; arrays padded).
__global__ __launch_bounds__(256) void volume_kernel(float* __restrict__ out,
                                                     int maxdisp) {
    int y  = blockIdx.x;
    int d0 = blockIdx.y * DPB;
    int ch = blockIdx.z;                 // 0=hamming, 1=|dCb|, 2=|dCr|
    int lane = threadIdx.x;
    int x = lane * 4;
    int rbase = y * W + x;
    int lb = rbase + d0;
    int rem = W - x - d0;                // element (dd, j) valid iff dd + j < rem
    size_t obase = ((size_t)(ch * maxdisp + d0) * H + y) * W + x;

    // PDL: block until prep_kernel has fully completed (all its stores visible).
    asm volatile("griddepcontrol.wait;");

    if (lane >= W / 4) return;

    if (ch == 0) {
        // Census hamming channel
        uint4 c4 = *reinterpret_cast<const uint4*>(&g_cR[rbase]);
        unsigned cR[4] = {c4.x, c4.y, c4.z, c4.w};
        unsigned cl[DPB + 4];
        #pragma unroll
        for (int g = 0; g < (DPB + 4) / 4; g++) {
            uint4 cv = *reinterpret_cast<const uint4*>(&g_cL[lb + 4 * g]);
            cl[4 * g + 0] = cv.x; cl[4 * g + 1] = cv.y; cl[4 * g + 2] = cv.z; cl[4 * g + 3] = cv.w;
        }
        #pragma unroll
        for (int dd = 0; dd < DPB; dd++) {
            float v[4];
            #pragma unroll
            for (int j = 0; j < 4; j++)
                v[j] = ((dd + j) < rem) ? (float)__popc(cl[dd + j] ^ cR[j]) : 0.0f;
            __stcs(reinterpret_cast<float4*>(&out[obase + (size_t)dd * HW]),
                   make_float4(v[0], v[1], v[2], v[3]));
        }
    } else {
        // Chroma abs-diff channel
        const float* L = (ch == 1) ? g_cbL : g_crL;
        const float* R = (ch == 1) ? g_cbR : g_crR;
        float4 r4 = *reinterpret_cast<const float4*>(&R[rbase]);
        float vR[4] = {r4.x, r4.y, r4.z, r4.w};
        float vl[DPB + 4];
        #pragma unroll
        for (int g = 0; g < (DPB + 4) / 4; g++) {
            float4 lv = *reinterpret_cast<const float4*>(&L[lb + 4 * g]);
            vl[4 * g + 0] = lv.x; vl[4 * g + 1] = lv.y; vl[4 * g + 2] = lv.z; vl[4 * g + 3] = lv.w;
        }
        #pragma unroll
        for (int dd = 0; dd < DPB; dd++) {
            float v[4];
            #pragma unroll
            for (int j = 0; j < 4; j++)
                v[j] = ((dd + j) < rem) ? fabsf(vl[dd + j] - vR[j]) : 0.0f;
            __stcs(reinterpret_cast<float4*>(&out[obase + (size_t)dd * HW]),
                   make_float4(v[0], v[1], v[2], v[3]));
        }
    }
}

extern "C" void kernel_launch(void* const* d_in, const int* in_sizes, int n_in,
                              void* d_out, int out_size) {
    const float* left  = (const float*)d_in[0];
    const float* right = (const float*)d_in[1];
    float* out = (float*)d_out;
    // maxdisp lives in device memory (d_in[2]); derive it host-side from out_size.
    int maxdisp = out_size / (3 * HW);   // = 128 for the bench shape

    dim3 pgrid(W / TX, H / TY, 2);       // 15 x 40 x 2
    prep_kernel<<<pgrid, 256>>>(left, right);

    // Volume kernel launched with PDL so its launch/prologue overlaps prep's tail.
    cudaLaunchConfig_t cfg = {};
    cfg.gridDim  = dim3(H, (maxdisp + DPB - 1) / DPB, 3);  // 320 x 8 x 3, y fastest
    cfg.blockDim = dim3(256, 1, 1);
    cfg.dynamicSmemBytes = 0;
    cfg.stream = 0;
    cudaLaunchAttribute attr[1];
    attr[0].id = cudaLaunchAttributeProgrammaticStreamSerialization;
    attr[0].val.programmaticStreamSerializationAllowed = 1;
    cfg.attrs = attr;
    cfg.numAttrs = 1;
    cudaLaunchKernelEx(&cfg, volume_kernel, out, maxdisp);
}

// round 17
// speedup vs baseline: 1.0068x; 1.0068x over previous
#include <cuda_runtime.h>
#include <cstdint>

#define H 320
#define W 960
#define HW (H * W)
#define PAD 128   // slack so left-window vector loads can't run past the array

// Fused prep tile config (64x16 interior, 2-px halo -> 25% halo row overhead)
#define TX 64
#define TY 16
#define SX (TX + 4)
#define SY (TY + 4)

// Disparities per volume block (multiple of 4 for aligned left loads)
#define DPB 8

// Scratch (allocation-free: __device__ globals). Y plane never hits global.
__device__ float g_cbL[HW + PAD], g_cbR[HW + PAD];
__device__ float g_crL[HW + PAD], g_crR[HW + PAD];
__device__ unsigned g_cL[HW + PAD], g_cR[HW + PAD];

// Fused YCbCr + census. One block per 64x16 tile per image (blockIdx.z).
__global__ __launch_bounds__(256) void prep_kernel(const float* __restrict__ left,
                                                   const float* __restrict__ right) {
    int img = blockIdx.z;
    const float* src = img ? right : left;
    float* cb    = img ? g_cbR : g_cbL;
    float* cr    = img ? g_crR : g_crL;
    unsigned* C  = img ? g_cR  : g_cL;

    __shared__ float sY[SY][SX];
    int tx0 = blockIdx.x * TX, ty0 = blockIdx.y * TY;

    // Phase 1: compute Y for tile+halo into smem; write cb/cr for interior.
    for (int idx = threadIdx.x; idx < SX * SY; idx += 256) {
        int sy = idx / SX, sx = idx - sy * SX;
        int gx = tx0 + sx - 2, gy = ty0 + sy - 2;
        float yv = 0.0f;
        if (gx >= 0 && gx < W && gy >= 0 && gy < H) {
            int p = gy * W + gx;
            float r = src[p], g = src[HW + p], b = src[2 * HW + p];
            yv = 0.299f * r + 0.587f * g + 0.114f * b;
            if (sx >= 2 && sx < SX - 2 && sy >= 2 && sy < SY - 2) {
                cb[p] = (b - yv) * 0.564f + 0.5f;
                cr[p] = (r - yv) * 0.713f + 0.5f;
            }
        }
        sY[sy][sx] = yv;
    }
    __syncthreads();

    // Phase 2: census from smem (4 passes of 256 threads over 64x16 interior).
    int px = threadIdx.x % TX;
    for (int py = threadIdx.x / TX; py < TY; py += 256 / TX) {
        int gx = tx0 + px, gy = ty0 + py;
        unsigned cen = 0u;
        if (gx >= 2 && gx < W - 2 && gy >= 2 && gy < H - 2) {
            float c = sY[py + 2][px + 2];
            #pragma unroll
            for (int v = 0; v < 5; v++) {
                #pragma unroll
                for (int u = 0; u < 5; u++) {
                    if (v == 1 && u == 1) continue;  // reference skips (1,1), NOT the center
                    cen = (cen << 1) | (sY[py + v][px + u] >= c ? 1u : 0u);
                }
            }
        }
        C[gy * W + gx] = cen;
    }

    // PDL: allow the dependent volume kernel to begin launching.
    asm volatile("griddepcontrol.launch_dependents;");
}

// Grid: (y=H fastest, d-group, channel). Per block: lanes 0..239 produce 4
// consecutive x for ONE channel across DPB=8 disparities. Concurrent blocks
// write consecutive y rows of one plane (DRAM page/burst locality — measured
// 73.6% DRAM vs 67% with d-fastest ordering). Stores use .cs streaming.
// Volume is pinned at ~69.8us / 6.03 TB/s across all measured variants:
// this is the DRAM-write ceiling for the pattern.
// Out-of-range lanes read neighbor-row garbage (masked on output; arrays padded).
__global__ __launch_bounds__(256) void volume_kernel(float* __restrict__ out,
                                                     int maxdisp) {
    int y  = blockIdx.x;
    int d0 = blockIdx.y * DPB;
    int ch = blockIdx.z;                 // 0=hamming, 1=|dCb|, 2=|dCr|
    int lane = threadIdx.x;
    int x = lane * 4;
    int rbase = y * W + x;
    int lb = rbase + d0;
    int rem = W - x - d0;                // element (dd, j) valid iff dd + j < rem
    size_t obase = ((size_t)(ch * maxdisp + d0) * H + y) * W + x;

    // PDL: block until prep_kernel has fully completed (all its stores visible).
    asm volatile("griddepcontrol.wait;");

    if (lane >= W / 4) return;

    if (ch == 0) {
        // Census hamming channel
        uint4 c4 = *reinterpret_cast<const uint4*>(&g_cR[rbase]);
        unsigned cR[4] = {c4.x, c4.y, c4.z, c4.w};
        unsigned cl[DPB + 4];
        #pragma unroll
        for (int g = 0; g < (DPB + 4) / 4; g++) {
            uint4 cv = *reinterpret_cast<const uint4*>(&g_cL[lb + 4 * g]);
            cl[4 * g + 0] = cv.x; cl[4 * g + 1] = cv.y; cl[4 * g + 2] = cv.z; cl[4 * g + 3] = cv.w;
        }
        #pragma unroll
        for (int dd = 0; dd < DPB; dd++) {
            float v[4];
            #pragma unroll
            for (int j = 0; j < 4; j++)
                v[j] = ((dd + j) < rem) ? (float)__popc(cl[dd + j] ^ cR[j]) : 0.0f;
            __stcs(reinterpret_cast<float4*>(&out[obase + (size_t)dd * HW]),
                   make_float4(v[0], v[1], v[2], v[3]));
        }
    } else {
        // Chroma abs-diff channel
        const float* L = (ch == 1) ? g_cbL : g_crL;
        const float* R = (ch == 1) ? g_cbR : g_crR;
        float4 r4 = *reinterpret_cast<const float4*>(&R[rbase]);
        float vR[4] = {r4.x, r4.y, r4.z, r4.w};
        float vl[DPB + 4];
        #pragma unroll
        for (int g = 0; g < (DPB + 4) / 4; g++) {
            float4 lv = *reinterpret_cast<const float4*>(&L[lb + 4 * g]);
            vl[4 * g + 0] = lv.x; vl[4 * g + 1] = lv.y; vl[4 * g + 2] = lv.z; vl[4 * g + 3] = lv.w;
        }
        #pragma unroll
        for (int dd = 0; dd < DPB; dd++) {
            float v[4];
            #pragma unroll
            for (int j = 0; j < 4; j++)
                v[j] = ((dd + j) < rem) ? fabsf(vl[dd + j] - vR[j]) : 0.0f;
            __stcs(reinterpret_cast<float4*>(&out[obase + (size_t)dd * HW]),
                   make_float4(v[0], v[1], v[2], v[3]));
        }
    }
}

extern "C" void kernel_launch(void* const* d_in, const int* in_sizes, int n_in,
                              void* d_out, int out_size) {
    const float* left  = (const float*)d_in[0];
    const float* right = (const float*)d_in[1];
    float* out = (float*)d_out;
    // maxdisp lives in device memory (d_in[2]); derive it host-side from out_size.
    int maxdisp = out_size / (3 * HW);   // = 128 for the bench shape

    dim3 pgrid(W / TX, H / TY, 2);       // 15 x 20 x 2
    prep_kernel<<<pgrid, 256>>>(left, right);

    // Volume kernel launched with PDL so its launch/prologue overlaps prep's tail.
    cudaLaunchConfig_t cfg = {};
    cfg.gridDim  = dim3(H, (maxdisp + DPB - 1) / DPB, 3);  // 320 x 16 x 3, y fastest
    cfg.blockDim = dim3(256, 1, 1);
    cfg.dynamicSmemBytes = 0;
    cfg.stream = 0;
    cudaLaunchAttribute attr[1];
    attr[0].id = cudaLaunchAttributeProgrammaticStreamSerialization;
    attr[0].val.programmaticStreamSerializationAllowed = 1;
    cfg.attrs = attr;
    cfg.numAttrs = 1;
    cudaLaunchKernelEx(&cfg, volume_kernel, out, maxdisp);
}